// round 12
// baseline (speedup 1.0000x reference)
#include <cuda_runtime.h>
#include <cuda_fp16.h>
#include <math.h>
#include <stdint.h>

// ---------------------------------------------------------------------------
// Problem constants (fixed instance)
// ---------------------------------------------------------------------------
constexpr int Bc  = 2;
constexpr int Cc  = 256;
constexpr int NHc = 8;
constexpr int Lc  = 4;
constexpr int Pc  = 4;
constexpr int LVc = 13294;       // 100*100 + 50*50 + 25*25 + 13*13
constexpr int LQc = 13294;
constexpr int Mrows = Bc * LQc;  // 26588
constexpr int PROJW = NHc * Lc * Pc * 2 + NHc * Lc * Pc; // 384

// Scratch (device globals; no allocation allowed)
// g_val is HEAD-MAJOR: [b][head][pixel][32ch] fp16 (64B per pixel per head)
__device__ __half g_val [Bc * NHc * LVc * 32];
__device__ __half g_proj[Bc * LQc * PROJW]; // [b][q][384] fp16
__device__ __half g_msda[Bc * LQc * Cc];    // [b][q][c]   fp16
__device__ float  g_wcat[Cc * PROJW];       // Woff || Wattn
__device__ float  g_bcat[PROJW];            // boff || battn

// ---------------------------------------------------------------------------
// fp16 MMA helpers
// ---------------------------------------------------------------------------
__device__ __forceinline__ uint32_t pack_h2(float a, float b) {
    __half2 h = __floats2half2_rn(a, b);
    return *reinterpret_cast<uint32_t*>(&h);
}
__device__ __forceinline__ void ldmatrix_x4(uint32_t (&r)[4], uint32_t saddr) {
    asm volatile("ldmatrix.sync.aligned.m8n8.x4.shared.b16 {%0,%1,%2,%3}, [%4];"
                 : "=r"(r[0]), "=r"(r[1]), "=r"(r[2]), "=r"(r[3])
                 : "r"(saddr));
}
__device__ __forceinline__ void mma_f16(float (&d)[4],
                                        const uint32_t (&a)[4],
                                        const uint32_t b0, const uint32_t b1) {
    asm volatile(
        "mma.sync.aligned.m16n8k16.row.col.f32.f16.f16.f32 "
        "{%0,%1,%2,%3}, {%4,%5,%6,%7}, {%8,%9}, {%0,%1,%2,%3};"
        : "+f"(d[0]), "+f"(d[1]), "+f"(d[2]), "+f"(d[3])
        : "r"(a[0]), "r"(a[1]), "r"(a[2]), "r"(a[3]), "r"(b0), "r"(b1));
}

// ---------------------------------------------------------------------------
// Weight/bias concat: g_wcat[k][n] = n<256 ? Woff[k][n] : Wattn[k][n-256]
// ---------------------------------------------------------------------------
__global__ void concat_w(const float* __restrict__ Woff,
                         const float* __restrict__ boff,
                         const float* __restrict__ Wattn,
                         const float* __restrict__ battn,
                         float* __restrict__ wcat, float* __restrict__ bcat)
{
    int i = blockIdx.x * 256 + threadIdx.x;
    if (i < Cc * PROJW) {
        int k = i / PROJW, n = i - k * PROJW;
        wcat[i] = (n < 256) ? Woff[k * 256 + n] : Wattn[k * 128 + n - 256];
    }
    if (i < PROJW) bcat[i] = (i < 256) ? boff[i] : battn[i - 256];
}

// ---------------------------------------------------------------------------
// Tensor-core FP16 GEMM (fp32 accum): Cout = A(MxK=256)*W(256xN)+bias(+resid)
//   A_ILV: A row m at A[(s*Bc+b)*256+k].
//   OUT_MODE 0: Cout[m*ldc+n]. OUT_MODE 1: residual + interleaved output.
//   OUT_MODE 2: head-major value layout ((b*8+h)*Lseq+s)*32+ch, fp16.
//   OUT_HALF: __half output. A_HALF: A is __half (direct copy staging).
// BM=128, BN=128, BK=32. 8 warps (2x4), warp tile 64x32, m16n8k16.
// ---------------------------------------------------------------------------
template<bool A_ILV, int OUT_MODE, bool OUT_HALF, bool A_HALF>
__global__ __launch_bounds__(256)
void hgemm_tc(const void* __restrict__ Ain, const float* __restrict__ W,
              const float* __restrict__ bias, void* __restrict__ Cout,
              int M, int Lseq, int ldw, int ldc,
              const float* __restrict__ resid)
{
    __shared__ __half    As[2][128][40];    // [stage][m][k-half]
    __shared__ uint32_t  Bp[2][16][136];    // [stage][kpair][n] packed half2

    const int tid  = threadIdx.x;
    const int warp = tid >> 5;
    const int lane = tid & 31;
    const int wm = warp >> 2;          // 0..1
    const int wn = warp & 3;           // 0..3
    const int m0 = blockIdx.x * 128;
    const int n0 = blockIdx.y * 128;
    const int qr = lane >> 2;          // 0..7
    const int qc = lane & 3;           // 0..3

    // ---- staging slots ----
    int arow[2], ac8[2];
    const void* aptr[2];
    #pragma unroll
    for (int r = 0; r < 2; r++) {
        int idx = tid + r * 256;
        arow[r] = idx >> 2;            // 0..127
        ac8[r]  = (idx & 3) * 8;       // element offset in k-tile
        int m = m0 + arow[r];
        if (m < M) {
            int off;
            if (A_ILV) { int b = m / Lseq; int s = m - b * Lseq;
                         off = (s * Bc + b) * Cc; }
            else       { off = m * Cc; }
            if (A_HALF) aptr[r] = (const __half*)Ain + off;
            else        aptr[r] = (const float*)Ain + off;
        } else aptr[r] = nullptr;
    }
    int wkp[2], wn4[2];
    #pragma unroll
    for (int r = 0; r < 2; r++) {
        int idx = tid + r * 256;
        wkp[r] = idx >> 5;             // 0..15
        wn4[r] = (idx & 31) * 4;       // 0..124
    }
    const float* wbase = W + n0;

    float acc[4][4][4];
    #pragma unroll
    for (int mt = 0; mt < 4; mt++)
        #pragma unroll
        for (int nt = 0; nt < 4; nt++)
            #pragma unroll
            for (int c = 0; c < 4; c++) acc[mt][nt][c] = 0.f;

    const float4 f4z = make_float4(0.f, 0.f, 0.f, 0.f);

    float4 na[2][2], nw[2][2];
    uint4 ua[2];
    auto load_tile = [&](int kb) {
        #pragma unroll
        for (int r = 0; r < 2; r++) {
            if (A_HALF) {
                if (aptr[r]) ua[r] = *(const uint4*)((const __half*)aptr[r] + kb + ac8[r]);
                else         ua[r] = make_uint4(0, 0, 0, 0);
            } else {
                if (aptr[r]) {
                    na[r][0] = *(const float4*)((const float*)aptr[r] + kb + ac8[r]);
                    na[r][1] = *(const float4*)((const float*)aptr[r] + kb + ac8[r] + 4);
                } else { na[r][0] = f4z; na[r][1] = f4z; }
            }
            nw[r][0] = *(const float4*)(wbase + (kb + 2 * wkp[r]    ) * ldw + wn4[r]);
            nw[r][1] = *(const float4*)(wbase + (kb + 2 * wkp[r] + 1) * ldw + wn4[r]);
        }
    };
    auto store_tile = [&](int st) {
        #pragma unroll
        for (int r = 0; r < 2; r++) {
            if (A_HALF) {
                *(uint4*)&As[st][arow[r]][ac8[r]] = ua[r];
            } else {
                uint4 a4;
                a4.x = pack_h2(na[r][0].x, na[r][0].y);
                a4.y = pack_h2(na[r][0].z, na[r][0].w);
                a4.z = pack_h2(na[r][1].x, na[r][1].y);
                a4.w = pack_h2(na[r][1].z, na[r][1].w);
                *(uint4*)&As[st][arow[r]][ac8[r]] = a4;
            }
            uint4 w4;
            w4.x = pack_h2(nw[r][0].x, nw[r][1].x);
            w4.y = pack_h2(nw[r][0].y, nw[r][1].y);
            w4.z = pack_h2(nw[r][0].z, nw[r][1].z);
            w4.w = pack_h2(nw[r][0].w, nw[r][1].w);
            *(uint4*)&Bp[st][wkp[r]][wn4[r]] = w4;
        }
    };

    load_tile(0);
    store_tile(0);
    __syncthreads();

    #pragma unroll 1
    for (int kk = 0; kk < Cc / 32; kk++) {
        const int cur = kk & 1;
        if (kk < Cc / 32 - 1) load_tile((kk + 1) * 32);

        #pragma unroll
        for (int ks = 0; ks < 32; ks += 16) {
            uint32_t afr[4][4];
            #pragma unroll
            for (int mt = 0; mt < 4; mt++) {
                int rowb = wm * 64 + mt * 16;
                int row = rowb + (lane & 7) + ((lane >> 3) & 1) * 8;
                int col = ks + (lane >> 4) * 8;
                uint32_t sa = (uint32_t)__cvta_generic_to_shared(&As[cur][row][col]);
                ldmatrix_x4(afr[mt], sa);
            }
            uint32_t bfr[4][2];
            #pragma unroll
            for (int nt = 0; nt < 4; nt++) {
                int col = wn * 32 + nt * 8 + qr;
                bfr[nt][0] = Bp[cur][ks / 2 + qc    ][col];
                bfr[nt][1] = Bp[cur][ks / 2 + qc + 4][col];
            }
            #pragma unroll
            for (int mt = 0; mt < 4; mt++)
                #pragma unroll
                for (int nt = 0; nt < 4; nt++)
                    mma_f16(acc[mt][nt], afr[mt], bfr[nt][0], bfr[nt][1]);
        }

        if (kk < Cc / 32 - 1) {
            store_tile(cur ^ 1);
            __syncthreads();
        }
    }

    // ---- epilogue ----
    float2 bvals[4];
    #pragma unroll
    for (int nt = 0; nt < 4; nt++) {
        int n = n0 + wn * 32 + nt * 8 + qc * 2;
        bvals[nt] = *(const float2*)&bias[n];
    }

    #pragma unroll
    for (int mt = 0; mt < 4; mt++) {
        #pragma unroll
        for (int hrow = 0; hrow < 2; hrow++) {
            int m = m0 + wm * 64 + mt * 16 + qr + hrow * 8;
            if (m >= M) continue;
            int obase;
            if (OUT_MODE == 1) {
                int b = m / Lseq; int s = m - b * Lseq;
                obase = (s * Bc + b) * Cc;
            } else if (OUT_MODE == 2) {
                int b = m / Lseq; int s = m - b * Lseq;
                int hh = (n0 + wn * 32) >> 5;       // head of this warp's slab
                obase = ((b * NHc + hh) * Lseq + s) * 32;  // + ch per nt
            } else {
                obase = m * ldc;
            }
            #pragma unroll
            for (int nt = 0; nt < 4; nt++) {
                int col = nt * 8 + qc * 2;          // 0..30 within slab
                int n = n0 + wn * 32 + col;
                float vx = acc[mt][nt][hrow * 2 + 0] + bvals[nt].x;
                float vy = acc[mt][nt][hrow * 2 + 1] + bvals[nt].y;
                if (OUT_MODE == 1) {
                    float2 rr = *(const float2*)&resid[obase + n];
                    vx += rr.x; vy += rr.y;
                }
                if (OUT_MODE == 2) {
                    __half2* op = (__half2*)((__half*)Cout + obase + col);
                    *op = __floats2half2_rn(vx, vy);
                } else if (OUT_HALF) {
                    __half2* op = (__half2*)((__half*)Cout + obase + n);
                    *op = __floats2half2_rn(vx, vy);
                } else {
                    *(float2*)((float*)Cout + obase + n) = make_float2(vx, vy);
                }
            }
        }
    }
}

// ---------------------------------------------------------------------------
// Fused softmax + bilinear sampling — head-major value layout.
// Warp gw: pair = gw>>3, head = gw&7; lane half (bit4) = query (bq=2*pair+half).
// Within 16-lane half: g2 = hl>>3 (point group, 2 in flight), xc = (hl>>2)&1
// (x-corner), cq3 = hl&3 (channel quad: 8 channels, 16B). The 8 lanes of one
// point cover the contiguous 128B x0|x1 pixel pair. 2 point-iterations/level.
// ---------------------------------------------------------------------------
#define SHFL16(v, s) __shfl_sync(0xffffffffu, (v), (s), 16)

__device__ __forceinline__ void corner_acc_h2(__half2 (&hacc)[4], const uint4* p,
                                              __half2 w) {
    uint4 u = *p;
    hacc[0] = __hfma2(*reinterpret_cast<__half2*>(&u.x), w, hacc[0]);
    hacc[1] = __hfma2(*reinterpret_cast<__half2*>(&u.y), w, hacc[1]);
    hacc[2] = __hfma2(*reinterpret_cast<__half2*>(&u.z), w, hacc[2]);
    hacc[3] = __hfma2(*reinterpret_cast<__half2*>(&u.w), w, hacc[3]);
}

__global__ __launch_bounds__(512, 3)
void msda_sample(const float* __restrict__ rp,
                 const __half* __restrict__ val,
                 const __half* __restrict__ proj,
                 __half* __restrict__ msda)
{
    const int gw   = (blockIdx.x * 512 + threadIdx.x) >> 5;
    const int lane = threadIdx.x & 31;
    const int pair = gw >> 3;
    const int h    = gw & 7;
    const int hl   = lane & 15;            // lane within query-half
    const int bq   = pair * 2 + (lane >> 4);
    const int g2   = hl >> 3;              // 0..1 point group
    const int xc   = (hl >> 2) & 1;        // x-corner (0: x0, 1: x1)
    const int cq3  = hl & 3;               // channel quad (8 ch, 16B)
    const int b    = bq / LQc;

    const __half* prow = proj + bq * PROJW;
    float off0 = __half2float(prow[h * 32 + hl]);        // offsets 0..15
    float off1 = __half2float(prow[h * 32 + 16 + hl]);   // offsets 16..31
    float lg   = __half2float(prow[256 + h * 16 + hl]);  // 16 logits
    float rpv  = 0.f;
    if (hl < 8) {
        rpv = rp[bq * (Lc * 2) + hl];
        rpv = fminf(fmaxf(rpv, 1e-5f), 1.f - 1e-5f);
    }

    // Softmax over 16 logits (xor 1..8 stays within each 16-lane half)
    float mx = lg;
    #pragma unroll
    for (int o = 8; o > 0; o >>= 1)
        mx = fmaxf(mx, __shfl_xor_sync(0xffffffffu, mx, o));
    float e = __expf(lg - mx);
    float sum = e;
    #pragma unroll
    for (int o = 8; o > 0; o >>= 1)
        sum += __shfl_xor_sync(0xffffffffu, sum, o);
    float attn_val = e / sum;

    constexpr int HH[4] = {100, 50, 25, 13};
    constexpr int ST[4] = {0, 10000, 12500, 13125};

    // Head-major: pixel = 64B = 4 uint4. Lane reads quad cq3 of pixel (x+xc).
    const uint4* vb = (const uint4*)val + (size_t)((b * NHc + h) * LVc) * 4 + cq3;

    float acc[8];
    #pragma unroll
    for (int j = 0; j < 8; j++) acc[j] = 0.f;

    #pragma unroll
    for (int l = 0; l < Lc; l++) {
        const int   Wl = HH[l];
        const int   st = ST[l];
        const float fW = (float)HH[l];

        float rpx = SHFL16(rpv, 2 * l);
        float rpy = SHFL16(rpv, 2 * l + 1);

        __half2 hz = __float2half2_rn(0.f);
        __half2 hacc[4] = {hz, hz, hz, hz};

        #pragma unroll
        for (int it = 0; it < 2; it++) {
            const int p = it * 2 + g2;          // point 0..3 (lane-dependent)
            const int oidx = l * 8 + 2 * p;
            float offx, offy;
            if (l < 2) { offx = SHFL16(off0, oidx);      offy = SHFL16(off0, oidx + 1); }
            else       { offx = SHFL16(off1, oidx - 16); offy = SHFL16(off1, oidx - 15); }
            float a = SHFL16(attn_val, l * 4 + p);

            float x = fmaf(rpx, fW, offx) - 0.5f;
            float y = fmaf(rpy, fW, offy) - 0.5f;
            float x0f = floorf(x), y0f = floorf(y);
            int x0 = (int)x0f, y0 = (int)y0f;
            float wx = x - x0f, wy = y - y0f;

            // This lane handles x-corner (x0 + xc)
            float wxc = xc ? wx : (1.f - wx);
            int   xi  = x0 + xc;
            bool  vx  = (xi >= 0) & (xi < Wl);
            bool  vy0 = (y0 >= 0) & (y0 < Wl);
            int   y1  = y0 + 1;
            bool  vy1 = (y1 >= 0) & (y1 < Wl);

            float w0 = a * (1.f - wy) * wxc;
            float w1 = a * wy * wxc;

            int pix0 = (st + y0 * Wl + xi) * 4;
            int pix1 = pix0 + Wl * 4;

            if (vy0 & vx) corner_acc_h2(hacc, vb + pix0, __float2half2_rn(w0));
            if (vy1 & vx) corner_acc_h2(hacc, vb + pix1, __float2half2_rn(w1));
        }

        // Fold level partial into fp32 master accumulator
        #pragma unroll
        for (int j = 0; j < 4; j++) {
            float2 t = __half22float2(hacc[j]);
            acc[2 * j]     += t.x;
            acc[2 * j + 1] += t.y;
        }
    }

    // Reduce across x-corners (xor 4) and point groups (xor 8)
    #pragma unroll
    for (int j = 0; j < 8; j++) {
        acc[j] += __shfl_xor_sync(0xffffffffu, acc[j], 4);
        acc[j] += __shfl_xor_sync(0xffffffffu, acc[j], 8);
    }

    if ((hl >> 2) == 0) {   // g2 == 0 && xc == 0
        uint4 o;
        o.x = pack_h2(acc[0], acc[1]);
        o.y = pack_h2(acc[2], acc[3]);
        o.z = pack_h2(acc[4], acc[5]);
        o.w = pack_h2(acc[6], acc[7]);
        ((uint4*)msda)[bq * 32 + h * 4 + cq3] = o;
    }
}

// ---------------------------------------------------------------------------
extern "C" void kernel_launch(void* const* d_in, const int* in_sizes, int n_in,
                              void* d_out, int out_size)
{
    const float* query = (const float*)d_in[0];   // (LQ, B, C)
    const float* rp    = (const float*)d_in[1];   // (B, LQ, L, 2)
    const float* value = (const float*)d_in[2];   // (LV, B, C)
    const float* Wv    = (const float*)d_in[5];
    const float* bv    = (const float*)d_in[6];
    const float* Woff  = (const float*)d_in[7];
    const float* boff  = (const float*)d_in[8];
    const float* Wattn = (const float*)d_in[9];
    const float* battn = (const float*)d_in[10];
    const float* Wo    = (const float*)d_in[11];
    const float* bo    = (const float*)d_in[12];
    float* out = (float*)d_out;

    __half *valp, *msdap, *projp;
    float *wcatp, *bcatp;
    cudaGetSymbolAddress((void**)&valp,  g_val);
    cudaGetSymbolAddress((void**)&projp, g_proj);
    cudaGetSymbolAddress((void**)&msdap, g_msda);
    cudaGetSymbolAddress((void**)&wcatp, g_wcat);
    cudaGetSymbolAddress((void**)&bcatp, g_bcat);

    const int gm = (Mrows + 127) / 128;   // 208

    // 0) concat Woff||Wattn, boff||battn
    concat_w<<<(Cc * PROJW + 255) / 256, 256>>>(Woff, boff, Wattn, battn,
                                                wcatp, bcatp);
    // 1) value projection -> fp16 g_val (head-major layout)
    hgemm_tc<true, 2, true, false><<<dim3(gm, 2), 256>>>(
        value, Wv, bv, valp, Mrows, LVc, 256, 256, nullptr);
    // 2) fused offset+attn projection -> fp16 g_proj
    hgemm_tc<true, 0, true, false><<<dim3(gm, 3), 256>>>(
        query, wcatp, bcatp, projp, Mrows, LQc, PROJW, PROJW, nullptr);
    // 3) softmax + bilinear sampling -> fp16 g_msda (2 queries per warp)
    msda_sample<<<(Mrows / 2 * NHc) / 16, 512>>>(rp, valp, projp, msdap);
    // 4) output projection + bias + residual -> d_out (A in fp16)
    hgemm_tc<false, 1, false, true><<<dim3(gm, 2), 256>>>(
        msdap, Wo, bo, out, Mrows, LQc, 256, 256, query);
}

// round 13
// speedup vs baseline: 1.0408x; 1.0408x over previous
#include <cuda_runtime.h>
#include <cuda_fp16.h>
#include <math.h>
#include <stdint.h>

// ---------------------------------------------------------------------------
// Problem constants (fixed instance)
// ---------------------------------------------------------------------------
constexpr int Bc  = 2;
constexpr int Cc  = 256;
constexpr int NHc = 8;
constexpr int Lc  = 4;
constexpr int Pc  = 4;
constexpr int LVc = 13294;       // 100*100 + 50*50 + 25*25 + 13*13
constexpr int LQc = 13294;
constexpr int Mrows = Bc * LQc;  // 26588
constexpr int PROJW = NHc * Lc * Pc * 2 + NHc * Lc * Pc; // 384

// Scratch (device globals; no allocation allowed)
__device__ __half g_val [Bc * LVc * Cc];    // [b][lv][c]  fp16
__device__ __half g_proj[Bc * LQc * PROJW]; // [b][q][384] fp16
__device__ __half g_msda[Bc * LQc * Cc];    // [b][q][c]   fp16

// ---------------------------------------------------------------------------
// fp16 MMA helpers
// ---------------------------------------------------------------------------
__device__ __forceinline__ uint32_t pack_h2(float a, float b) {
    __half2 h = __floats2half2_rn(a, b);
    return *reinterpret_cast<uint32_t*>(&h);
}
__device__ __forceinline__ void ldmatrix_x4(uint32_t (&r)[4], uint32_t saddr) {
    asm volatile("ldmatrix.sync.aligned.m8n8.x4.shared.b16 {%0,%1,%2,%3}, [%4];"
                 : "=r"(r[0]), "=r"(r[1]), "=r"(r[2]), "=r"(r[3])
                 : "r"(saddr));
}
__device__ __forceinline__ void mma_f16(float (&d)[4],
                                        const uint32_t (&a)[4],
                                        const uint32_t b0, const uint32_t b1) {
    asm volatile(
        "mma.sync.aligned.m16n8k16.row.col.f32.f16.f16.f32 "
        "{%0,%1,%2,%3}, {%4,%5,%6,%7}, {%8,%9}, {%0,%1,%2,%3};"
        : "+f"(d[0]), "+f"(d[1]), "+f"(d[2]), "+f"(d[3])
        : "r"(a[0]), "r"(a[1]), "r"(a[2]), "r"(a[3]), "r"(b0), "r"(b1));
}

// ---------------------------------------------------------------------------
// FUSED projection GEMMs (value-proj + offset-proj + attn-proj) in one grid.
// blockIdx.y dispatch (gm x 5 blocks):
//   y=0,1 : g_val[m][y*128 .. ]   = value @ Wv[:, y*128..]   + bv     (ldc 256)
//   y=2,3 : g_proj[m][(y-2)*128..] = query @ Woff[:, ..]     + boff   (ldc 384)
//   y=4   : g_proj[m][256..384]    = query @ Wattn           + battn  (ldc 384)
// A rows interleaved: m = b*13294 + s at A[(s*2+b)*256 + k]. fp16 out.
// BM=128, BN=128, BK=32, 8 warps (2x4), warp tile 64x32, m16n8k16.
// ---------------------------------------------------------------------------
__global__ __launch_bounds__(256)
void hgemm_proj_fused(const float* __restrict__ value,
                      const float* __restrict__ query,
                      const float* __restrict__ Wv,   const float* __restrict__ bv,
                      const float* __restrict__ Woff, const float* __restrict__ boff,
                      const float* __restrict__ Wattn,const float* __restrict__ battn,
                      __half* __restrict__ valp, __half* __restrict__ projp)
{
    __shared__ __half    As[2][128][40];    // [stage][m][k-half]
    __shared__ uint32_t  Bp[2][16][136];    // [stage][kpair][n] packed half2

    const int tid  = threadIdx.x;
    const int warp = tid >> 5;
    const int lane = tid & 31;
    const int wm = warp >> 2;          // 0..1
    const int wn = warp & 3;           // 0..3
    const int m0 = blockIdx.x * 128;
    const int gy = blockIdx.y;
    const int qr = lane >> 2;          // 0..7
    const int qc = lane & 3;           // 0..3

    // ---- dispatch ----
    const float* A;  const float* W;  const float* bias;
    __half* Cout;  int ldw, ldc, outc0;
    if (gy < 2) {
        A = value; W = Wv + gy * 128;   bias = bv + gy * 128;
        Cout = valp;  ldw = 256; ldc = 256; outc0 = gy * 128;
    } else if (gy < 4) {
        A = query; W = Woff + (gy - 2) * 128; bias = boff + (gy - 2) * 128;
        Cout = projp; ldw = 256; ldc = PROJW; outc0 = (gy - 2) * 128;
    } else {
        A = query; W = Wattn; bias = battn;
        Cout = projp; ldw = 128; ldc = PROJW; outc0 = 256;
    }

    // ---- staging slots ----
    int arow[2], ac8[2];
    const float* aptr[2];
    #pragma unroll
    for (int r = 0; r < 2; r++) {
        int idx = tid + r * 256;
        arow[r] = idx >> 2;            // 0..127
        ac8[r]  = (idx & 3) * 8;       // element offset in k-tile
        int m = m0 + arow[r];
        if (m < Mrows) {
            int b = m / LQc; int s = m - b * LQc;
            aptr[r] = A + (s * Bc + b) * Cc;
        } else aptr[r] = nullptr;
    }
    int wkp[2], wn4[2];
    #pragma unroll
    for (int r = 0; r < 2; r++) {
        int idx = tid + r * 256;
        wkp[r] = idx >> 5;             // 0..15
        wn4[r] = (idx & 31) * 4;       // 0..124
    }

    float acc[4][4][4];
    #pragma unroll
    for (int mt = 0; mt < 4; mt++)
        #pragma unroll
        for (int nt = 0; nt < 4; nt++)
            #pragma unroll
            for (int c = 0; c < 4; c++) acc[mt][nt][c] = 0.f;

    const float4 f4z = make_float4(0.f, 0.f, 0.f, 0.f);

    float4 na[2][2], nw[2][2];
    auto load_tile = [&](int kb) {
        #pragma unroll
        for (int r = 0; r < 2; r++) {
            if (aptr[r]) {
                na[r][0] = *(const float4*)(aptr[r] + kb + ac8[r]);
                na[r][1] = *(const float4*)(aptr[r] + kb + ac8[r] + 4);
            } else { na[r][0] = f4z; na[r][1] = f4z; }
            nw[r][0] = *(const float4*)(W + (kb + 2 * wkp[r]    ) * ldw + wn4[r]);
            nw[r][1] = *(const float4*)(W + (kb + 2 * wkp[r] + 1) * ldw + wn4[r]);
        }
    };
    auto store_tile = [&](int st) {
        #pragma unroll
        for (int r = 0; r < 2; r++) {
            uint4 a4;
            a4.x = pack_h2(na[r][0].x, na[r][0].y);
            a4.y = pack_h2(na[r][0].z, na[r][0].w);
            a4.z = pack_h2(na[r][1].x, na[r][1].y);
            a4.w = pack_h2(na[r][1].z, na[r][1].w);
            *(uint4*)&As[st][arow[r]][ac8[r]] = a4;
            uint4 w4;
            w4.x = pack_h2(nw[r][0].x, nw[r][1].x);
            w4.y = pack_h2(nw[r][0].y, nw[r][1].y);
            w4.z = pack_h2(nw[r][0].z, nw[r][1].z);
            w4.w = pack_h2(nw[r][0].w, nw[r][1].w);
            *(uint4*)&Bp[st][wkp[r]][wn4[r]] = w4;
        }
    };

    load_tile(0);
    store_tile(0);
    __syncthreads();

    #pragma unroll 1
    for (int kk = 0; kk < Cc / 32; kk++) {
        const int cur = kk & 1;
        if (kk < Cc / 32 - 1) load_tile((kk + 1) * 32);

        #pragma unroll
        for (int ks = 0; ks < 32; ks += 16) {
            uint32_t afr[4][4];
            #pragma unroll
            for (int mt = 0; mt < 4; mt++) {
                int rowb = wm * 64 + mt * 16;
                int row = rowb + (lane & 7) + ((lane >> 3) & 1) * 8;
                int col = ks + (lane >> 4) * 8;
                uint32_t sa = (uint32_t)__cvta_generic_to_shared(&As[cur][row][col]);
                ldmatrix_x4(afr[mt], sa);
            }
            uint32_t bfr[4][2];
            #pragma unroll
            for (int nt = 0; nt < 4; nt++) {
                int col = wn * 32 + nt * 8 + qr;
                bfr[nt][0] = Bp[cur][ks / 2 + qc    ][col];
                bfr[nt][1] = Bp[cur][ks / 2 + qc + 4][col];
            }
            #pragma unroll
            for (int mt = 0; mt < 4; mt++)
                #pragma unroll
                for (int nt = 0; nt < 4; nt++)
                    mma_f16(acc[mt][nt], afr[mt], bfr[nt][0], bfr[nt][1]);
        }

        if (kk < Cc / 32 - 1) {
            store_tile(cur ^ 1);
            __syncthreads();
        }
    }

    // ---- epilogue: fp16 output ----
    float2 bvals[4];
    #pragma unroll
    for (int nt = 0; nt < 4; nt++) {
        bvals[nt] = *(const float2*)&bias[wn * 32 + nt * 8 + qc * 2];
    }

    #pragma unroll
    for (int mt = 0; mt < 4; mt++) {
        #pragma unroll
        for (int hrow = 0; hrow < 2; hrow++) {
            int m = m0 + wm * 64 + mt * 16 + qr + hrow * 8;
            if (m >= Mrows) continue;
            int obase = m * ldc + outc0;
            #pragma unroll
            for (int nt = 0; nt < 4; nt++) {
                int col = wn * 32 + nt * 8 + qc * 2;
                float vx = acc[mt][nt][hrow * 2 + 0] + bvals[nt].x;
                float vy = acc[mt][nt][hrow * 2 + 1] + bvals[nt].y;
                __half2* op = (__half2*)(Cout + obase + col);
                *op = __floats2half2_rn(vx, vy);
            }
        }
    }
}

// ---------------------------------------------------------------------------
// Output-projection GEMM: out = g_msda(fp16) @ Wo + bo + query (residual),
// output interleaved (s*2+b)*256. BM=128, BN=128, BK=32, as before.
// ---------------------------------------------------------------------------
__global__ __launch_bounds__(256)
void hgemm_out(const __half* __restrict__ Ain, const float* __restrict__ W,
               const float* __restrict__ bias, float* __restrict__ Cout,
               const float* __restrict__ resid)
{
    __shared__ __half    As[2][128][40];
    __shared__ uint32_t  Bp[2][16][136];

    const int tid  = threadIdx.x;
    const int warp = tid >> 5;
    const int lane = tid & 31;
    const int wm = warp >> 2;
    const int wn = warp & 3;
    const int m0 = blockIdx.x * 128;
    const int n0 = blockIdx.y * 128;
    const int qr = lane >> 2;
    const int qc = lane & 3;

    int arow[2], ac8[2];
    const __half* aptr[2];
    #pragma unroll
    for (int r = 0; r < 2; r++) {
        int idx = tid + r * 256;
        arow[r] = idx >> 2;
        ac8[r]  = (idx & 3) * 8;
        int m = m0 + arow[r];
        aptr[r] = (m < Mrows) ? Ain + m * Cc : nullptr;
    }
    int wkp[2], wn4[2];
    #pragma unroll
    for (int r = 0; r < 2; r++) {
        int idx = tid + r * 256;
        wkp[r] = idx >> 5;
        wn4[r] = (idx & 31) * 4;
    }
    const float* wbase = W + n0;

    float acc[4][4][4];
    #pragma unroll
    for (int mt = 0; mt < 4; mt++)
        #pragma unroll
        for (int nt = 0; nt < 4; nt++)
            #pragma unroll
            for (int c = 0; c < 4; c++) acc[mt][nt][c] = 0.f;

    uint4 ua[2];
    float4 nw[2][2];
    auto load_tile = [&](int kb) {
        #pragma unroll
        for (int r = 0; r < 2; r++) {
            ua[r] = aptr[r] ? *(const uint4*)(aptr[r] + kb + ac8[r])
                            : make_uint4(0, 0, 0, 0);
            nw[r][0] = *(const float4*)(wbase + (kb + 2 * wkp[r]    ) * Cc + wn4[r]);
            nw[r][1] = *(const float4*)(wbase + (kb + 2 * wkp[r] + 1) * Cc + wn4[r]);
        }
    };
    auto store_tile = [&](int st) {
        #pragma unroll
        for (int r = 0; r < 2; r++) {
            *(uint4*)&As[st][arow[r]][ac8[r]] = ua[r];
            uint4 w4;
            w4.x = pack_h2(nw[r][0].x, nw[r][1].x);
            w4.y = pack_h2(nw[r][0].y, nw[r][1].y);
            w4.z = pack_h2(nw[r][0].z, nw[r][1].z);
            w4.w = pack_h2(nw[r][0].w, nw[r][1].w);
            *(uint4*)&Bp[st][wkp[r]][wn4[r]] = w4;
        }
    };

    load_tile(0);
    store_tile(0);
    __syncthreads();

    #pragma unroll 1
    for (int kk = 0; kk < Cc / 32; kk++) {
        const int cur = kk & 1;
        if (kk < Cc / 32 - 1) load_tile((kk + 1) * 32);

        #pragma unroll
        for (int ks = 0; ks < 32; ks += 16) {
            uint32_t afr[4][4];
            #pragma unroll
            for (int mt = 0; mt < 4; mt++) {
                int rowb = wm * 64 + mt * 16;
                int row = rowb + (lane & 7) + ((lane >> 3) & 1) * 8;
                int col = ks + (lane >> 4) * 8;
                uint32_t sa = (uint32_t)__cvta_generic_to_shared(&As[cur][row][col]);
                ldmatrix_x4(afr[mt], sa);
            }
            uint32_t bfr[4][2];
            #pragma unroll
            for (int nt = 0; nt < 4; nt++) {
                int col = wn * 32 + nt * 8 + qr;
                bfr[nt][0] = Bp[cur][ks / 2 + qc    ][col];
                bfr[nt][1] = Bp[cur][ks / 2 + qc + 4][col];
            }
            #pragma unroll
            for (int mt = 0; mt < 4; mt++)
                #pragma unroll
                for (int nt = 0; nt < 4; nt++)
                    mma_f16(acc[mt][nt], afr[mt], bfr[nt][0], bfr[nt][1]);
        }

        if (kk < Cc / 32 - 1) {
            store_tile(cur ^ 1);
            __syncthreads();
        }
    }

    float2 bvals[4];
    #pragma unroll
    for (int nt = 0; nt < 4; nt++) {
        bvals[nt] = *(const float2*)&bias[n0 + wn * 32 + nt * 8 + qc * 2];
    }

    #pragma unroll
    for (int mt = 0; mt < 4; mt++) {
        #pragma unroll
        for (int hrow = 0; hrow < 2; hrow++) {
            int m = m0 + wm * 64 + mt * 16 + qr + hrow * 8;
            if (m >= Mrows) continue;
            int b = m / LQc; int s = m - b * LQc;
            int obase = (s * Bc + b) * Cc;
            #pragma unroll
            for (int nt = 0; nt < 4; nt++) {
                int n = n0 + wn * 32 + nt * 8 + qc * 2;
                float vx = acc[mt][nt][hrow * 2 + 0] + bvals[nt].x;
                float vy = acc[mt][nt][hrow * 2 + 1] + bvals[nt].y;
                float2 rr = *(const float2*)&resid[obase + n];
                vx += rr.x; vy += rr.y;
                *(float2*)&Cout[obase + n] = make_float2(vx, vy);
            }
        }
    }
}

// ---------------------------------------------------------------------------
// Fused softmax + bilinear sampling — 2 queries/warp, 4 points in parallel,
// 8 channels per lane (LDG.128), per-level HFMA2 corner accumulation.
// (R11-best configuration, channel-major g_val.)
// ---------------------------------------------------------------------------
#define SHFL16(v, s) __shfl_sync(0xffffffffu, (v), (s), 16)

__device__ __forceinline__ void corner_acc_h2(__half2 (&hacc)[4], const uint4* p,
                                              __half2 w) {
    uint4 u = *p;
    hacc[0] = __hfma2(*reinterpret_cast<__half2*>(&u.x), w, hacc[0]);
    hacc[1] = __hfma2(*reinterpret_cast<__half2*>(&u.y), w, hacc[1]);
    hacc[2] = __hfma2(*reinterpret_cast<__half2*>(&u.z), w, hacc[2]);
    hacc[3] = __hfma2(*reinterpret_cast<__half2*>(&u.w), w, hacc[3]);
}

__global__ __launch_bounds__(512, 3)
void msda_sample(const float* __restrict__ rp,
                 const __half* __restrict__ val,
                 const __half* __restrict__ proj,
                 __half* __restrict__ msda)
{
    const int gw   = (blockIdx.x * 512 + threadIdx.x) >> 5;
    const int lane = threadIdx.x & 31;
    const int pair = gw >> 3;
    const int h    = gw & 7;
    const int hl   = lane & 15;            // lane within query-half
    const int bq   = pair * 2 + (lane >> 4);
    const int g4   = hl >> 2;              // 0..3 point group
    const int cq   = hl & 3;               // channel octet (8 ch)
    const int b    = bq / LQc;

    const __half* prow = proj + bq * PROJW;
    float off0 = __half2float(prow[h * 32 + hl]);        // offsets 0..15
    float off1 = __half2float(prow[h * 32 + 16 + hl]);   // offsets 16..31
    float lg   = __half2float(prow[256 + h * 16 + hl]);  // 16 logits
    float rpv  = 0.f;
    if (hl < 8) {
        rpv = rp[bq * (Lc * 2) + hl];
        rpv = fminf(fmaxf(rpv, 1e-5f), 1.f - 1e-5f);
    }

    // Softmax over 16 logits (xor 1..8 stays within each 16-lane half)
    float mx = lg;
    #pragma unroll
    for (int o = 8; o > 0; o >>= 1)
        mx = fmaxf(mx, __shfl_xor_sync(0xffffffffu, mx, o));
    float e = __expf(lg - mx);
    float sum = e;
    #pragma unroll
    for (int o = 8; o > 0; o >>= 1)
        sum += __shfl_xor_sync(0xffffffffu, sum, o);
    float attn_val = e / sum;

    constexpr int HH[4] = {100, 50, 25, 13};
    constexpr int ST[4] = {0, 10000, 12500, 13125};

    // uint4 units: 256 halves/pixel = 32 uint4; lane covers 8 channels
    const uint4* vb = (const uint4*)val + (b * LVc) * 32 + h * 4 + cq;

    float acc[8];
    #pragma unroll
    for (int j = 0; j < 8; j++) acc[j] = 0.f;

    #pragma unroll
    for (int l = 0; l < Lc; l++) {
        const int   Wl = HH[l];
        const int   st = ST[l];
        const float fW = (float)HH[l];

        float rpx = SHFL16(rpv, 2 * l);
        float rpy = SHFL16(rpv, 2 * l + 1);

        const int oidx = l * 8 + 2 * g4;   // offset-pair index for this point
        float offx, offy;
        if (l < 2) { offx = SHFL16(off0, oidx);      offy = SHFL16(off0, oidx + 1); }
        else       { offx = SHFL16(off1, oidx - 16); offy = SHFL16(off1, oidx - 15); }
        float a = SHFL16(attn_val, l * 4 + g4);

        float x = fmaf(rpx, fW, offx) - 0.5f;
        float y = fmaf(rpy, fW, offy) - 0.5f;
        float x0f = floorf(x), y0f = floorf(y);
        int x0 = (int)x0f, y0 = (int)y0f;
        float wx = x - x0f, wy = y - y0f;

        float w00 = a * (1.f - wy) * (1.f - wx);
        float w01 = a * (1.f - wy) * wx;
        float w10 = a * wy * (1.f - wx);
        float w11 = a * wy * wx;

        int x1 = x0 + 1, y1 = y0 + 1;
        bool vx0 = (x0 >= 0) & (x0 < Wl);
        bool vx1 = (x1 >= 0) & (x1 < Wl);
        bool vy0 = (y0 >= 0) & (y0 < Wl);
        bool vy1 = (y1 >= 0) & (y1 < Wl);

        int row0 = (st + y0 * Wl) * 32;
        int row1 = row0 + Wl * 32;

        // Per-level fp16 corner accumulation (4 HFMA2 per corner)
        __half2 hz = __float2half2_rn(0.f);
        __half2 hacc[4] = {hz, hz, hz, hz};
        if (vy0 & vx0) corner_acc_h2(hacc, vb + row0 + x0 * 32, __float2half2_rn(w00));
        if (vy0 & vx1) corner_acc_h2(hacc, vb + row0 + x1 * 32, __float2half2_rn(w01));
        if (vy1 & vx0) corner_acc_h2(hacc, vb + row1 + x0 * 32, __float2half2_rn(w10));
        if (vy1 & vx1) corner_acc_h2(hacc, vb + row1 + x1 * 32, __float2half2_rn(w11));

        // Fold level partial into fp32 master accumulator
        #pragma unroll
        for (int j = 0; j < 4; j++) {
            float2 t = __half22float2(hacc[j]);
            acc[2 * j]     += t.x;
            acc[2 * j + 1] += t.y;
        }
    }

    // Reduce across the 4 point-groups (hl bits 2,3 -> xor 4, xor 8)
    #pragma unroll
    for (int j = 0; j < 8; j++) {
        acc[j] += __shfl_xor_sync(0xffffffffu, acc[j], 4);
        acc[j] += __shfl_xor_sync(0xffffffffu, acc[j], 8);
    }

    if (g4 == 0) {
        uint4 o;
        o.x = pack_h2(acc[0], acc[1]);
        o.y = pack_h2(acc[2], acc[3]);
        o.z = pack_h2(acc[4], acc[5]);
        o.w = pack_h2(acc[6], acc[7]);
        ((uint4*)msda)[bq * 32 + h * 4 + cq] = o;
    }
}

// ---------------------------------------------------------------------------
extern "C" void kernel_launch(void* const* d_in, const int* in_sizes, int n_in,
                              void* d_out, int out_size)
{
    const float* query = (const float*)d_in[0];   // (LQ, B, C)
    const float* rp    = (const float*)d_in[1];   // (B, LQ, L, 2)
    const float* value = (const float*)d_in[2];   // (LV, B, C)
    const float* Wv    = (const float*)d_in[5];
    const float* bv    = (const float*)d_in[6];
    const float* Woff  = (const float*)d_in[7];
    const float* boff  = (const float*)d_in[8];
    const float* Wattn = (const float*)d_in[9];
    const float* battn = (const float*)d_in[10];
    const float* Wo    = (const float*)d_in[11];
    const float* bo    = (const float*)d_in[12];
    float* out = (float*)d_out;

    __half *valp, *msdap, *projp;
    cudaGetSymbolAddress((void**)&valp,  g_val);
    cudaGetSymbolAddress((void**)&projp, g_proj);
    cudaGetSymbolAddress((void**)&msdap, g_msda);

    const int gm = (Mrows + 127) / 128;   // 208

    // 1) all projections in ONE launch (1040 blocks): g_val + g_proj
    hgemm_proj_fused<<<dim3(gm, 5), 256>>>(value, query, Wv, bv,
                                           Woff, boff, Wattn, battn,
                                           valp, projp);
    // 2) softmax + bilinear sampling -> fp16 g_msda
    msda_sample<<<(Mrows / 2 * NHc) / 16, 512>>>(rp, valp, projp, msdap);
    // 3) output projection + bias + residual -> d_out
    hgemm_out<<<dim3(gm, 2), 256>>>(msdap, Wo, bo, out, query);
}